// round 1
// baseline (speedup 1.0000x reference)
#include <cuda_runtime.h>
#include <cuda_bf16.h>
#include <math.h>

// ---------------- problem constants ----------------
#define PB 64      // batch
#define PS 48      // seq len
#define PE 256     // embed dim
#define PH 512     // hidden
#define PV 30000   // vocab
#define PH2 1024   // 2H
#define PH3 1536   // 3H

// ---------------- device scratch (no allocs allowed) ----------------
__device__ float g_h[2][PB * PH];          // ping-pong hidden state
__device__ float g_enc[PB * PS * PH];      // encoder states [B][S][H]
__device__ float g_cat[PB * PH2];          // [h_new, context] per batch
__device__ int   g_tok[PB];                // decoder feedback tokens
__device__ float g_pred_scratch[PS * PB];  // fallback if out holds only dists

// ---------------- init ----------------
__global__ void init_kernel() {
    int t = blockIdx.x * blockDim.x + threadIdx.x;
    if (t < PB * PH) g_h[0][t] = 0.0f;
    if (t < PB) g_tok[t] = 0;
}

// ---------------- GRU step: warp per (b, j) unit ----------------
// grid: (B*H/8) blocks of 256 threads (8 warps)
__global__ void gru_kernel(const int* __restrict__ tok_base, int tok_stride,
                           const float* __restrict__ embed,
                           const float* __restrict__ wih,
                           const float* __restrict__ whh,
                           const float* __restrict__ bih,
                           const float* __restrict__ bhh,
                           int hin_sel, int hout_sel, int enc_step) {
    int g    = blockIdx.x * 8 + (threadIdx.x >> 5);
    int lane = threadIdx.x & 31;
    int b = g >> 9;          // / 512
    int j = g & 511;

    const int* tb = tok_base ? tok_base : g_tok;
    int tok = tb[b * tok_stride];

    const float* x    = embed + (size_t)tok * PE;
    const float* hrow = g_h[hin_sel] + b * PH;

    const float* wi0 = wih + (size_t)j * PE;
    const float* wi1 = wi0 + (size_t)PH * PE;
    const float* wi2 = wi1 + (size_t)PH * PE;
    const float* wh0 = whh + (size_t)j * PH;
    const float* wh1 = wh0 + (size_t)PH * PH;
    const float* wh2 = wh1 + (size_t)PH * PH;

    float air = 0.f, aiz = 0.f, ain = 0.f, ahr = 0.f, ahz = 0.f, ahn = 0.f;
#pragma unroll
    for (int k = lane; k < PE; k += 32) {
        float xv = x[k];
        air = fmaf(wi0[k], xv, air);
        aiz = fmaf(wi1[k], xv, aiz);
        ain = fmaf(wi2[k], xv, ain);
    }
#pragma unroll
    for (int k = lane; k < PH; k += 32) {
        float hv = hrow[k];
        ahr = fmaf(wh0[k], hv, ahr);
        ahz = fmaf(wh1[k], hv, ahz);
        ahn = fmaf(wh2[k], hv, ahn);
    }
#pragma unroll
    for (int o = 16; o > 0; o >>= 1) {
        air += __shfl_xor_sync(0xFFFFFFFFu, air, o);
        aiz += __shfl_xor_sync(0xFFFFFFFFu, aiz, o);
        ain += __shfl_xor_sync(0xFFFFFFFFu, ain, o);
        ahr += __shfl_xor_sync(0xFFFFFFFFu, ahr, o);
        ahz += __shfl_xor_sync(0xFFFFFFFFu, ahz, o);
        ahn += __shfl_xor_sync(0xFFFFFFFFu, ahn, o);
    }
    if (lane == 0) {
        float pre_r = air + bih[j] + ahr + bhh[j];
        float pre_z = aiz + bih[j + PH] + ahz + bhh[j + PH];
        float r = 1.0f / (1.0f + __expf(-pre_r));
        float z = 1.0f / (1.0f + __expf(-pre_z));
        float n = tanhf(ain + bih[j + 2 * PH] + r * (ahn + bhh[j + 2 * PH]));
        float hn = (1.0f - z) * n + z * hrow[j];
        g_h[hout_sel][b * PH + j] = hn;
        if (enc_step >= 0)
            g_enc[(size_t)b * PS * PH + (size_t)enc_step * PH + j] = hn;
    }
}

// ---------------- attention + cat: one block per batch row ----------------
__global__ void attn_kernel(int hsel) {
    __shared__ float sh[PH];
    __shared__ float sc[PS];
    __shared__ float sw[PS];
    int b = blockIdx.x;
    int tid = threadIdx.x;       // 128 threads
    int warp = tid >> 5, lane = tid & 31;

    const float* h = g_h[hsel] + b * PH;
    for (int k = tid; k < PH; k += 128) sh[k] = h[k];
    __syncthreads();

    for (int s = warp; s < PS; s += 4) {
        const float* e = g_enc + ((size_t)b * PS + s) * PH;
        float acc = 0.f;
#pragma unroll
        for (int k = lane; k < PH; k += 32) acc = fmaf(e[k], sh[k], acc);
#pragma unroll
        for (int o = 16; o > 0; o >>= 1) acc += __shfl_xor_sync(0xFFFFFFFFu, acc, o);
        if (lane == 0) sc[s] = acc;
    }
    __syncthreads();

    float mx = -INFINITY;
#pragma unroll
    for (int s = 0; s < PS; s++) mx = fmaxf(mx, sc[s]);
    if (tid < PS) sw[tid] = __expf(sc[tid] - mx);
    __syncthreads();

    float ssum = 0.f;
#pragma unroll
    for (int s = 0; s < PS; s++) ssum += sw[s];
    float inv = 1.0f / ssum;

    for (int jc = tid; jc < PH; jc += 128) {
        float acc = 0.f;
        const float* e = g_enc + (size_t)b * PS * PH + jc;
#pragma unroll 8
        for (int s = 0; s < PS; s++) acc = fmaf(sw[s], e[(size_t)s * PH], acc);
        g_cat[b * PH2 + PH + jc] = acc * inv;
        g_cat[b * PH2 + jc]      = sh[jc];
    }
}

// ---------------- projection GEMM: logits[64 x 30000] = cat @ W^T + b ----------------
// BM=64, BN=256, BK=16; 256 threads; 8x8 register tile per thread.
#define PBN 256
#define PBK 16
__global__ void __launch_bounds__(256, 2)
proj_kernel(const float* __restrict__ W, const float* __restrict__ bias,
            float* __restrict__ out /* [64][V], row stride V */) {
    __shared__ float As[PBK][PB];
    __shared__ float Bs[PBK][PBN];
    int tid = threadIdx.x;
    int tx = tid & 31;      // column group (8 cols each)
    int ty = tid >> 5;      // row group (8 rows each)
    int n0 = blockIdx.x * PBN;

    float acc[8][8];
#pragma unroll
    for (int i = 0; i < 8; i++)
#pragma unroll
        for (int jj = 0; jj < 8; jj++) acc[i][jj] = 0.f;

    const float* A = g_cat;
    for (int k0 = 0; k0 < PH2; k0 += PBK) {
        if (tid < PB) {
            const float4* ap = (const float4*)(A + tid * PH2 + k0);
            float4 a0 = ap[0], a1 = ap[1], a2 = ap[2], a3 = ap[3];
            As[0][tid] = a0.x;  As[1][tid] = a0.y;  As[2][tid] = a0.z;  As[3][tid] = a0.w;
            As[4][tid] = a1.x;  As[5][tid] = a1.y;  As[6][tid] = a1.z;  As[7][tid] = a1.w;
            As[8][tid] = a2.x;  As[9][tid] = a2.y;  As[10][tid] = a2.z; As[11][tid] = a2.w;
            As[12][tid] = a3.x; As[13][tid] = a3.y; As[14][tid] = a3.z; As[15][tid] = a3.w;
        }
        int v = n0 + tid;
        float4 b0 = {0,0,0,0}, b1 = {0,0,0,0}, b2 = {0,0,0,0}, b3 = {0,0,0,0};
        if (v < PV) {
            const float4* bp = (const float4*)(W + (size_t)v * PH2 + k0);
            b0 = bp[0]; b1 = bp[1]; b2 = bp[2]; b3 = bp[3];
        }
        Bs[0][tid] = b0.x;  Bs[1][tid] = b0.y;  Bs[2][tid] = b0.z;  Bs[3][tid] = b0.w;
        Bs[4][tid] = b1.x;  Bs[5][tid] = b1.y;  Bs[6][tid] = b1.z;  Bs[7][tid] = b1.w;
        Bs[8][tid] = b2.x;  Bs[9][tid] = b2.y;  Bs[10][tid] = b2.z; Bs[11][tid] = b2.w;
        Bs[12][tid] = b3.x; Bs[13][tid] = b3.y; Bs[14][tid] = b3.z; Bs[15][tid] = b3.w;
        __syncthreads();

#pragma unroll
        for (int kk = 0; kk < PBK; kk++) {
            float4 aa0 = *(const float4*)&As[kk][ty * 8];
            float4 aa1 = *(const float4*)&As[kk][ty * 8 + 4];
            float4 bb0 = *(const float4*)&Bs[kk][tx * 8];
            float4 bb1 = *(const float4*)&Bs[kk][tx * 8 + 4];
            float a[8] = {aa0.x, aa0.y, aa0.z, aa0.w, aa1.x, aa1.y, aa1.z, aa1.w};
            float bb[8] = {bb0.x, bb0.y, bb0.z, bb0.w, bb1.x, bb1.y, bb1.z, bb1.w};
#pragma unroll
            for (int i = 0; i < 8; i++)
#pragma unroll
                for (int jj = 0; jj < 8; jj++)
                    acc[i][jj] = fmaf(a[i], bb[jj], acc[i][jj]);
        }
        __syncthreads();
    }

    int vbase = n0 + tx * 8;
    if (vbase < PV) {   // V % 8 == 0: each thread's 8 cols all valid or all invalid
        float4 bs0 = *(const float4*)&bias[vbase];
        float4 bs1 = *(const float4*)&bias[vbase + 4];
        float bb[8] = {bs0.x, bs0.y, bs0.z, bs0.w, bs1.x, bs1.y, bs1.z, bs1.w};
#pragma unroll
        for (int i = 0; i < 8; i++) {
            int m = ty * 8 + i;
            float4 o0 = {acc[i][0] + bb[0], acc[i][1] + bb[1], acc[i][2] + bb[2], acc[i][3] + bb[3]};
            float4 o1 = {acc[i][4] + bb[4], acc[i][5] + bb[5], acc[i][6] + bb[6], acc[i][7] + bb[7]};
            *(float4*)&out[(size_t)m * PV + vbase]     = o0;
            *(float4*)&out[(size_t)m * PV + vbase + 4] = o1;
        }
    }
}

// ---------------- log-softmax + argmax (in-place on logits row), feed back token ----------------
__global__ void softmax_kernel(float* __restrict__ row_base, float* __restrict__ pred) {
    __shared__ float smx[256];
    __shared__ int   smi[256];
    __shared__ float ssm[256];
    int b = blockIdx.x;
    int tid = threadIdx.x;
    float* p = row_base + (size_t)b * PV;

    // pass 1: max + argmax (first occurrence wins ties)
    float mx = -INFINITY; int mi = 0x7FFFFFFF;
    for (int v = tid; v < PV; v += 256) {
        float val = p[v];
        if (val > mx) { mx = val; mi = v; }
    }
    smx[tid] = mx; smi[tid] = mi;
    __syncthreads();
    for (int o = 128; o > 0; o >>= 1) {
        if (tid < o) {
            float v2 = smx[tid + o]; int i2 = smi[tid + o];
            if (v2 > smx[tid] || (v2 == smx[tid] && i2 < smi[tid])) { smx[tid] = v2; smi[tid] = i2; }
        }
        __syncthreads();
    }
    mx = smx[0]; mi = smi[0];
    __syncthreads();

    // pass 2: sum exp
    float s = 0.f;
    for (int v = tid; v < PV; v += 256) s += __expf(p[v] - mx);
    ssm[tid] = s;
    __syncthreads();
    for (int o = 128; o > 0; o >>= 1) {
        if (tid < o) ssm[tid] += ssm[tid + o];
        __syncthreads();
    }
    float lse = logf(ssm[0]);

    // pass 3: in-place log-softmax
    for (int v = tid; v < PV; v += 256) p[v] = p[v] - mx - lse;

    if (tid == 0) {
        pred[b] = (float)mi;
        g_tok[b] = mi;
    }
}

// ---------------- launch ----------------
extern "C" void kernel_launch(void* const* d_in, const int* in_sizes, int n_in,
                              void* d_out, int out_size) {
    const int*   input     = (const int*)d_in[0];
    const float* enc_embed = (const float*)d_in[1];
    const float* enc_wih   = (const float*)d_in[2];
    const float* enc_whh   = (const float*)d_in[3];
    const float* enc_bih   = (const float*)d_in[4];
    const float* enc_bhh   = (const float*)d_in[5];
    const float* dec_embed = (const float*)d_in[6];
    const float* dec_wih   = (const float*)d_in[7];
    const float* dec_whh   = (const float*)d_in[8];
    const float* dec_bih   = (const float*)d_in[9];
    const float* dec_bhh   = (const float*)d_in[10];
    const float* proj_w    = (const float*)d_in[11];
    const float* proj_b    = (const float*)d_in[12];

    float* out = (float*)d_out;
    size_t need_both = (size_t)PS * PB * PV + (size_t)PS * PB;
    float *pred, *dists;
    if ((size_t)out_size >= need_both) {
        pred  = out;            // predicted [S,B] first (reference return order)
        dists = out + PS * PB;  // then dists [S,B,V]
    } else {
        dists = out;            // only dists fit -> pred to scratch
        void* sp = nullptr;
        cudaGetSymbolAddress(&sp, g_pred_scratch);
        pred = (float*)sp;
    }

    init_kernel<<<128, 256>>>();

    const int GRU_BLOCKS = (PB * PH) / 8;   // 4096
    // ---- encoder ----
    for (int s = 0; s < PS; s++) {
        gru_kernel<<<GRU_BLOCKS, 256>>>(input + s, PS, enc_embed,
                                        enc_wih, enc_whh, enc_bih, enc_bhh,
                                        s & 1, (s + 1) & 1, s);
    }
    // encoder final h lands in g_h[0] (48 even); decoder continues ping-pong from there.
    // ---- decoder ----
    const int PROJ_BLOCKS = (PV + PBN - 1) / PBN;  // 118
    for (int t = 0; t < PS; t++) {
        gru_kernel<<<GRU_BLOCKS, 256>>>(nullptr, 1, dec_embed,
                                        dec_wih, dec_whh, dec_bih, dec_bhh,
                                        t & 1, (t + 1) & 1, -1);
        attn_kernel<<<PB, 128>>>((t + 1) & 1);
        proj_kernel<<<PROJ_BLOCKS, 256>>>(proj_w, proj_b,
                                          dists + (size_t)t * PB * PV);
        softmax_kernel<<<PB, 256>>>(dists + (size_t)t * PB * PV, pred + (size_t)t * PB);
    }
}